// round 7
// baseline (speedup 1.0000x reference)
#include <cuda_runtime.h>
#include <math.h>

#define NP 8732
#define NG 16
#define NC 21
#define NTHREADS 1024
#define NWARPS 32
#define NTILES 273

__device__ float g_bll[256];
__device__ float g_blc[256];
__device__ int   g_bnp[256];
__device__ unsigned g_arrive = 0;

struct __align__(16) Smem {
    float  stage[NWARPS * 672];    // conf staging; aliased as radix hist later
    float  lc[NP];
    float  tg[NG * 11];
    float4 box[NG];
    float  taa[NG];
    unsigned char gp[NP + 4];      // gi | (pos<<4)
    unsigned rqv[NG * NWARPS];
    int    rqi[NG * NWARPS];
    int    bp[NG];
    float  rf[NWARPS];
    float  rf2[NWARPS];
    int    ri[NWARPS];
    unsigned gsum[NWARPS];
    int    bc[4];
    float  dll[NG];
    float  dlc[NG];
    int    dnp[NG];
};

// smooth-L1 loc loss; single implementation for bit-identical math everywhere
__device__ __forceinline__ float sl1_calc(const float* __restrict__ ld,
                                          float4 pr, const float* t) {
    float vx = 0.1f * pr.z;
    float vy = 0.1f * pr.w;
    float lts[10];
    lts[0] = ((t[0] + t[2]) * 0.5f - pr.x) / vx;
    lts[1] = ((t[1] + t[3]) * 0.5f - pr.y) / vy;
    lts[2] = logf((t[2] - t[0]) / pr.z) / 0.2f;
    lts[3] = logf((t[3] - t[1]) / pr.w) / 0.2f;
    lts[4] = logf(t[4] / pr.z + 0.1f) / 0.2f;
    lts[5] = logf(t[5] / pr.w + 0.1f) / 0.2f;
    lts[6] = logf(t[6] / pr.z + 0.1f) / 0.2f;
    lts[7] = logf(t[7] / pr.w + 0.1f) / 0.2f;
    lts[8] = (t[8] - pr.x) / vx;
    lts[9] = (t[9] - pr.y) / vy;
    float ll = 0.0f;
#pragma unroll
    for (int j = 0; j < 10; j++) {
        float d  = __ldg(ld + j) - lts[j];
        float ad = fabsf(d);
        ll += (ad < 1.0f) ? (0.5f * d) * d : (ad - 0.5f);
    }
    return ll;
}

__global__ void __launch_bounds__(NTHREADS, 1) mb_main(
    const float* __restrict__ loc_data,   // [B, NP, 10]
    const float* __restrict__ conf_data,  // [B, NP, 21]
    const float* __restrict__ priors,     // [NP, 4]
    const float* __restrict__ targets,    // [B, NG, 11]
    float* __restrict__ out)
{
    extern __shared__ char smem_raw[];
    Smem* S = (Smem*)smem_raw;
    unsigned* hist = (unsigned*)S->stage;

    const int b    = blockIdx.x;
    const int tid  = threadIdx.x;
    const int lane = tid & 31;
    const int wrp  = tid >> 5;

    for (int i = tid; i < NG * 11; i += NTHREADS)
        S->tg[i] = targets[b * NG * 11 + i];
    __syncthreads();
    if (tid < NG) {
        const float* t = S->tg + tid * 11;
        float4 bx = make_float4(t[0], t[1], t[2], t[3]);
        S->box[tid] = bx;
        S->taa[tid] = (bx.z - bx.x) * (bx.w - bx.y);
    }
    __syncthreads();

    // ---- fused pass: matching + losses, register-prefetch pipelined ----
    unsigned rqb = 0u;            // lane g (<16): running best q bits for gt g
    int      rqi_ = 0x7fffffff;   // and its prior index
    float ll = 0.0f, lcp = 0.0f;
    int   np = 0;
    float* stg = S->stage + wrp * 672;
    float4* stg4 = (float4*)stg;
    const float* confb = conf_data + (size_t)b * NP * NC;

    float4 c0, c1, c2, c3, c4, c5;
    float4 pr = make_float4(0.f, 0.f, 1.f, 1.f);
    {
        const int p0 = wrp * 32;
        const int cnt = (NP - p0 < 32) ? (NP - p0) : 32;
        const int tcnt4 = (cnt * NC) >> 2;
        const float4* cb4 = (const float4*)(confb + (size_t)p0 * NC);
        if (lane < tcnt4)       c0 = __ldg(cb4 + lane);
        if (32 + lane < tcnt4)  c1 = __ldg(cb4 + 32 + lane);
        if (64 + lane < tcnt4)  c2 = __ldg(cb4 + 64 + lane);
        if (96 + lane < tcnt4)  c3 = __ldg(cb4 + 96 + lane);
        if (128 + lane < tcnt4) c4 = __ldg(cb4 + 128 + lane);
        if (160 + lane < tcnt4) c5 = __ldg(cb4 + 160 + lane);
        if (p0 + lane < NP) pr = __ldg((const float4*)priors + p0 + lane);
    }

#pragma unroll 1
    for (int tile = wrp; tile < NTILES; tile += NWARPS) {
        const int p0 = tile * 32;
        const int cnt = (NP - p0 < 32) ? (NP - p0) : 32;
        const int tcnt4 = (cnt * NC) >> 2;
        const int p = p0 + lane;
        const bool pv = p < NP;

        // commit current tile's conf to smem
        if (lane < tcnt4)       stg4[lane] = c0;
        if (32 + lane < tcnt4)  stg4[32 + lane] = c1;
        if (64 + lane < tcnt4)  stg4[64 + lane] = c2;
        if (96 + lane < tcnt4)  stg4[96 + lane] = c3;
        if (128 + lane < tcnt4) stg4[128 + lane] = c4;
        if (160 + lane < tcnt4) stg4[160 + lane] = c5;
        float4 cpr = pr;

        // prefetch next tile (loads fly during matching + LSE)
        const int nt = tile + NWARPS;
        if (nt < NTILES) {
            const int np0 = nt * 32;
            const int ncnt = (NP - np0 < 32) ? (NP - np0) : 32;
            const int ntc4 = (ncnt * NC) >> 2;
            const float4* ncb4 = (const float4*)(confb + (size_t)np0 * NC);
            if (lane < ntc4)       c0 = __ldg(ncb4 + lane);
            if (32 + lane < ntc4)  c1 = __ldg(ncb4 + 32 + lane);
            if (64 + lane < ntc4)  c2 = __ldg(ncb4 + 64 + lane);
            if (96 + lane < ntc4)  c3 = __ldg(ncb4 + 96 + lane);
            if (128 + lane < ntc4) c4 = __ldg(ncb4 + 128 + lane);
            if (160 + lane < ntc4) c5 = __ldg(ncb4 + 160 + lane);
            if (np0 + lane < NP) pr = __ldg((const float4*)priors + np0 + lane);
        }

        // matching for this tile (q = fast quotient; decisions validated in R5)
        float pax = cpr.x - 0.5f * cpr.z;
        float pay = cpr.y - 0.5f * cpr.w;
        float pbx = cpr.x + 0.5f * cpr.z;
        float pby = cpr.y + 0.5f * cpr.w;
        float pare = (pbx - pax) * (pby - pay);
        float bq = -1.0f;
        int bg = 0;
#pragma unroll
        for (int g = 0; g < NG; g++) {
            float4 t = S->box[g];
            float ix = fminf(t.z, pbx) - fmaxf(t.x, pax);
            float iy = fminf(t.w, pby) - fmaxf(t.y, pay);
            ix = fmaxf(ix, 0.0f);
            iy = fmaxf(iy, 0.0f);
            float inter = ix * iy;
            float den = (S->taa[g] + pare) - inter;   // > 0
            float q = __fdividef(inter, den);
            if (q > bq) { bq = q; bg = g; }           // first-max over g

            // warp-collective per-g argmax over this tile's 32 priors
            unsigned qb = pv ? __float_as_uint(q) : 0u;   // q >= 0: bits monotone
            unsigned m = __reduce_max_sync(0xffffffffu, qb);
            unsigned win = __ballot_sync(0xffffffffu, pv && (qb == m));
            int widx = p0 + (__ffs(win) - 1);             // lowest lane = lowest p
            if (lane == g) {
                if (m > rqb || (m == rqb && widx < rqi_)) { rqb = m; rqi_ = widx; }
            }
        }
        if (pv)
            S->gp[p] = (unsigned char)bg | ((bq >= 0.5f) ? 0x10 : 0x00);
        __syncwarp();

        if (pv) {
            bool pos = (bq >= 0.5f);
            int conf = pos ? ((int)S->tg[bg * 11 + 10] + 1) : 0;
            const float* row = stg + lane * NC;
            float s = 0.0f;
#pragma unroll
            for (int j = 0; j < NC; j++) s += __expf(row[j]);
            float lca = __logf(s) - row[conf];
            float lcv = lca;
            if (pos) {
                lcv = 0.0f;
                np++;
                lcp += lca;
                ll += sl1_calc(loc_data + ((size_t)b * NP + p) * 10, cpr,
                               S->tg + bg * 11);
            }
            S->lc[p] = lcv;
        }
        __syncwarp();
    }

    // ---- per-gt argmax: per-warp results -> block reduce -> bp ----
    if (lane < NG) {
        S->rqv[lane * NWARPS + wrp] = rqb;
        S->rqi[lane * NWARPS + wrp] = rqi_;
    }
    __syncthreads();
    if (tid < NG) {
        unsigned q = S->rqv[tid * NWARPS];
        int      i = S->rqi[tid * NWARPS];
        for (int w = 1; w < NWARPS; w++) {
            unsigned q2 = S->rqv[tid * NWARPS + w];
            int      i2 = S->rqi[tid * NWARPS + w];
            if (q2 > q || (q2 == q && i2 < i)) { q = q2; i = i2; }
        }
        S->bp[tid] = i;
    }
    __syncthreads();

    // ---- block reduce raw np / ll / lcp ----
#pragma unroll
    for (int o = 16; o > 0; o >>= 1) {
        ll  += __shfl_down_sync(0xffffffffu, ll, o);
        lcp += __shfl_down_sync(0xffffffffu, lcp, o);
        np  += __shfl_down_sync(0xffffffffu, np, o);
    }
    if (lane == 0) { S->rf[wrp] = ll; S->rf2[wrp] = lcp; S->ri[wrp] = np; }

    // ---- corrections for overridden priors (<=16), exact semantics ----
    if (tid < NG) {
        const int j = tid;
        const int p = S->bp[j];
        bool last = true;
#pragma unroll
        for (int j2 = j + 1; j2 < NG; j2++)
            if (S->bp[j2] == p) last = false;
        float dll = 0.0f, dlc = 0.0f;
        int dnp = 0;
        if (last) {
            unsigned old = S->gp[p];
            int gio = old & 15;
            bool poso = (old & 0x10) != 0;
            if (!(poso && gio == j)) {
                const float* c = conf_data + ((size_t)b * NP + p) * NC;
                float s = 0.0f;
#pragma unroll
                for (int j2 = 0; j2 < NC; j2++) s += __expf(__ldg(c + j2));
                float lse = __logf(s);
                const float* tn = S->tg + j * 11;
                int cn = (int)tn[10] + 1;
                float4 pr2 = __ldg((const float4*)priors + p);
                const float* ld = loc_data + ((size_t)b * NP + p) * 10;
                dlc = lse - __ldg(c + cn);
                dll = sl1_calc(ld, pr2, tn);
                dnp = poso ? 0 : 1;
                if (poso) {
                    const float* to = S->tg + gio * 11;
                    int co = (int)to[10] + 1;
                    dlc -= (lse - __ldg(c + co));
                    dll -= sl1_calc(ld, pr2, to);
                }
            }
            S->lc[p] = 0.0f;
        }
        S->dll[j] = dll;
        S->dlc[j] = dlc;
        S->dnp[j] = dnp;
    }
    __syncthreads();
    if (tid < 32) {
        float ll_t = S->rf[tid], lcp_t = S->rf2[tid];
        int   np_t = S->ri[tid];
#pragma unroll
        for (int o = 16; o > 0; o >>= 1) {
            ll_t  += __shfl_down_sync(0xffffffffu, ll_t, o);
            lcp_t += __shfl_down_sync(0xffffffffu, lcp_t, o);
            np_t  += __shfl_down_sync(0xffffffffu, np_t, o);
        }
        if (tid == 0) {
#pragma unroll
            for (int j = 0; j < NG; j++) {
                ll_t  += S->dll[j];
                lcp_t += S->dlc[j];
                np_t  += S->dnp[j];
            }
            S->rf[0] = ll_t; S->rf2[0] = lcp_t; S->bc[0] = np_t;
        }
    }
    __syncthreads();
    const int np_tot = S->bc[0];
    const float ll_tot = S->rf[0];
    const float lcp_tot = S->rf2[0];
    int k = 3 * np_tot;
    if (k > NP - 1) k = NP - 1;

    // ---- exact top-k sum via 3-round radix select ----
    float Ssum = 0.0f;
    if (k > 0) {
        unsigned prefix = 0u, pmask = 0u;
        const int shifts[3] = {21, 10, 0};
        const int rbits[3]  = {11, 11, 10};
        int kk = k;
        for (int r = 0; r < 3; r++) {
            for (int i = tid; i < 2048; i += NTHREADS) hist[i] = 0u;
            __syncthreads();
            const unsigned nb = 1u << rbits[r];
#pragma unroll 1
            for (int p = tid; p < 9216; p += NTHREADS) {
                bool valid = p < NP;
                unsigned bb = valid ? __float_as_uint(S->lc[p]) : 0u;
                bool sel = valid && ((bb & pmask) == prefix);
                unsigned bin = sel ? ((bb >> shifts[r]) & (nb - 1u)) : 0xffffffffu;
                unsigned grp = __match_any_sync(0xffffffffu, bin);
                if (sel && lane == (__ffs(grp) - 1))
                    atomicAdd(&hist[bin], (unsigned)__popc(grp));
            }
            __syncthreads();
            unsigned h0 = hist[tid * 2 + 0], h1 = hist[tid * 2 + 1];
            unsigned sloc = h0 + h1;
            unsigned suf = sloc;
#pragma unroll
            for (int o = 1; o < 32; o <<= 1) {
                unsigned v = __shfl_down_sync(0xffffffffu, suf, o);
                if (lane + o < 32) suf += v;
            }
            if (lane == 0) S->gsum[wrp] = suf;
            __syncthreads();
            unsigned above = 0;
            for (int w = wrp + 1; w < NWARPS; w++) above += S->gsum[w];
            unsigned excl1 = above + (suf - sloc);
            unsigned excl0 = excl1 + h1;
            unsigned ukk = (unsigned)kk;
            if (excl1 < ukk && ukk <= excl1 + h1) { S->bc[1] = tid * 2 + 1; S->bc[2] = (int)(ukk - excl1); }
            if (excl0 < ukk && ukk <= excl0 + h0) { S->bc[1] = tid * 2 + 0; S->bc[2] = (int)(ukk - excl0); }
            __syncthreads();
            int chosen = S->bc[1];
            kk = S->bc[2];
            prefix |= ((unsigned)chosen) << shifts[r];
            pmask  |= ((1u << rbits[r]) - 1u) << shifts[r];
            __syncthreads();
        }
        const float tv = __uint_as_float(prefix);
        float sgt = 0.0f;
        int   cgt = 0;
#pragma unroll 1
        for (int p = tid; p < NP; p += NTHREADS) {
            float v = S->lc[p];
            if (__float_as_uint(v) > prefix) { sgt += v; cgt++; }
        }
#pragma unroll
        for (int o = 16; o > 0; o >>= 1) {
            sgt += __shfl_down_sync(0xffffffffu, sgt, o);
            cgt += __shfl_down_sync(0xffffffffu, cgt, o);
        }
        if (lane == 0) { S->rf[wrp] = sgt; S->ri[wrp] = cgt; }
        __syncthreads();
        if (tid == 0) {
            float sgt_t = 0.0f;
            int   cgt_t = 0;
            for (int w = 0; w < NWARPS; w++) { sgt_t += S->rf[w]; cgt_t += S->ri[w]; }
            Ssum = sgt_t + (float)(k - cgt_t) * tv;
        }
    }

    // ---- publish per-batch partials; last CTA finalizes ----
    __shared__ bool slast;
    if (tid == 0) {
        g_bll[b] = ll_tot;
        g_blc[b] = lcp_tot + Ssum;
        g_bnp[b] = np_tot;
        __threadfence();
        unsigned t = atomicAdd(&g_arrive, 1u);
        slast = (t == gridDim.x - 1);
        if (slast) g_arrive = 0u;
    }
    __syncthreads();
    if (slast) {
        float fll = 0.0f, flc = 0.0f;
        int   fnp = 0;
        for (int i = tid; i < (int)gridDim.x; i += NTHREADS) {
            fll += g_bll[i]; flc += g_blc[i]; fnp += g_bnp[i];
        }
#pragma unroll
        for (int o = 16; o > 0; o >>= 1) {
            fll += __shfl_down_sync(0xffffffffu, fll, o);
            flc += __shfl_down_sync(0xffffffffu, flc, o);
            fnp += __shfl_down_sync(0xffffffffu, fnp, o);
        }
        if (lane == 0) { S->rf[wrp] = fll; S->rf2[wrp] = flc; S->ri[wrp] = fnp; }
        __syncthreads();
        if (tid == 0) {
            float tll = 0.0f, tlc = 0.0f;
            int tnp = 0;
            for (int w = 0; w < NWARPS; w++) { tll += S->rf[w]; tlc += S->rf2[w]; tnp += S->ri[w]; }
            float N = (float)tnp;
            out[0] = tll / N;
            out[1] = tlc / N;
        }
    }
}

extern "C" void kernel_launch(void* const* d_in, const int* in_sizes, int n_in,
                              void* d_out, int out_size) {
    const float* loc     = (const float*)d_in[0];
    const float* conf    = (const float*)d_in[1];
    const float* priors  = (const float*)d_in[2];
    const float* targets = (const float*)d_in[3];
    const int B = in_sizes[0] / (NP * 10);

    cudaFuncSetAttribute(mb_main, cudaFuncAttributeMaxDynamicSharedMemorySize,
                         (int)sizeof(Smem));
    mb_main<<<B, NTHREADS, sizeof(Smem)>>>(loc, conf, priors, targets, (float*)d_out);
}

// round 8
// speedup vs baseline: 1.0940x; 1.0940x over previous
#include <cuda_runtime.h>
#include <math.h>

#define NP 8732
#define NG 16
#define NC 21
#define NTHREADS 1024
#define NWARPS 32
#define NTILES 273

__device__ float g_bll[256];
__device__ float g_blc[256];
__device__ int   g_bnp[256];
__device__ unsigned g_arrive = 0;

struct __align__(16) Smem {
    float  stage[NWARPS * 672];    // conf staging; aliased as radix hist later
    float  lc[NP];
    float  tg[NG * 11];
    float4 box[NG];
    float  taa[NG];
    unsigned char gp[NP + 4];      // gi | (pos<<4)
    float  rqv[NG * NWARPS];
    int    rqi[NG * NWARPS];
    int    bp[NG];
    float  rf[NWARPS];
    float  rf2[NWARPS];
    int    ri[NWARPS];
    unsigned gsum[NWARPS];
    int    bc[4];
};

__global__ void __launch_bounds__(NTHREADS, 1) mb_main(
    const float* __restrict__ loc_data,   // [B, NP, 10]
    const float* __restrict__ conf_data,  // [B, NP, 21]
    const float* __restrict__ priors,     // [NP, 4]
    const float* __restrict__ targets,    // [B, NG, 11]
    float* __restrict__ out)
{
    extern __shared__ char smem_raw[];
    Smem* S = (Smem*)smem_raw;
    unsigned* hist = (unsigned*)S->stage;

    const int b    = blockIdx.x;
    const int tid  = threadIdx.x;
    const int lane = tid & 31;
    const int wrp  = tid >> 5;

    for (int i = tid; i < NG * 11; i += NTHREADS)
        S->tg[i] = targets[b * NG * 11 + i];
    __syncthreads();
    if (tid < NG) {
        const float* t = S->tg + tid * 11;
        float4 bx = make_float4(t[0], t[1], t[2], t[3]);
        S->box[tid] = bx;
        S->taa[tid] = (bx.z - bx.x) * (bx.w - bx.y);
    }
    __syncthreads();

    // ---- pass 1: matching; single fast-quotient decision system ----
    float qv[NG];
    int   qi[NG];
#pragma unroll
    for (int g = 0; g < NG; g++) { qv[g] = -1.0f; qi[g] = 0x7fffffff; }

#pragma unroll 1
    for (int p = tid; p < NP; p += NTHREADS) {
        float4 pr = __ldg((const float4*)priors + p);
        float pax = pr.x - 0.5f * pr.z;
        float pay = pr.y - 0.5f * pr.w;
        float pbx = pr.x + 0.5f * pr.z;
        float pby = pr.y + 0.5f * pr.w;
        float pare = (pbx - pax) * (pby - pay);
        float bq = -1.0f;
        int bg = 0;
#pragma unroll
        for (int g = 0; g < NG; g++) {
            float4 t = S->box[g];
            float ix = fminf(t.z, pbx) - fmaxf(t.x, pax);
            float iy = fminf(t.w, pby) - fmaxf(t.y, pay);
            ix = fmaxf(ix, 0.0f);
            iy = fmaxf(iy, 0.0f);
            float inter = ix * iy;
            float den = (S->taa[g] + pare) - inter;   // > 0
            float q = __fdividef(inter, den);
            if (q > bq) { bq = q; bg = g; }           // strict > : first max over g
            if (q > qv[g]) { qv[g] = q; qi[g] = p; }  // p ascending: first max over p
        }
        S->gp[p] = (unsigned char)bg | ((bq >= 0.5f) ? 0x10 : 0x00);
    }

    // warp reduce per gt (q desc, idx asc)
#pragma unroll
    for (int g = 0; g < NG; g++) {
        float q = qv[g];
        int   i = qi[g];
#pragma unroll
        for (int o = 16; o > 0; o >>= 1) {
            float q2 = __shfl_down_sync(0xffffffffu, q, o);
            int   i2 = __shfl_down_sync(0xffffffffu, i, o);
            if (q2 > q || (q2 == q && i2 < i)) { q = q2; i = i2; }
        }
        if (lane == 0) { S->rqv[g * NWARPS + wrp] = q; S->rqi[g * NWARPS + wrp] = i; }
    }
    __syncthreads();
    if (tid < NG) {
        float q = S->rqv[tid * NWARPS];
        int   i = S->rqi[tid * NWARPS];
        for (int w = 1; w < NWARPS; w++) {
            float q2 = S->rqv[tid * NWARPS + w];
            int   i2 = S->rqi[tid * NWARPS + w];
            if (q2 > q || (q2 == q && i2 < i)) { q = q2; i = i2; }
        }
        S->bp[tid] = i;
    }
    __syncthreads();
    if (tid == 0) {
#pragma unroll
        for (int j = 0; j < NG; j++) S->gp[S->bp[j]] = (unsigned char)j | 0x10;  // last wins
    }
    __syncthreads();

    // ---- pass 2: per-prior losses (coalesced staging, no-max LSE) ----
    float ll = 0.0f, lcp = 0.0f;
    int   np = 0;
    float* stg = S->stage + wrp * 672;
    float4* stg4 = (float4*)stg;
    const float* confb = conf_data + (size_t)b * NP * NC;

#pragma unroll 1
    for (int tile = wrp; tile < NTILES; tile += NWARPS) {
        const int p0 = tile * 32;
        const int cnt = (NP - p0 < 32) ? (NP - p0) : 32;
        const int tcnt4 = (cnt * NC) >> 2;
        const float4* cb4 = (const float4*)(confb + (size_t)p0 * NC);
#pragma unroll
        for (int j = 0; j < 6; j++) {
            int idx2 = j * 32 + lane;
            if (idx2 < tcnt4) stg4[idx2] = __ldg(cb4 + idx2);
        }
        __syncwarp();

        const int p = p0 + lane;
        if (p < NP) {
            unsigned gpv = S->gp[p];
            int gi = gpv & 15;
            bool pos = (gpv & 0x10) != 0;
            int conf = pos ? ((int)S->tg[gi * 11 + 10] + 1) : 0;

            const float* row = stg + lane * NC;
            float s = 0.0f;
#pragma unroll
            for (int j = 0; j < NC; j++) s += __expf(row[j]);
            float lca = __logf(s) - row[conf];

            float lc = lca;
            if (pos) {
                lc = 0.0f;
                np++;
                lcp += lca;
                const float* t = S->tg + gi * 11;
                float4 pr = __ldg((const float4*)priors + p);
                float vx = 0.1f * pr.z;
                float vy = 0.1f * pr.w;
                float lts[10];
                lts[0] = ((t[0] + t[2]) * 0.5f - pr.x) / vx;
                lts[1] = ((t[1] + t[3]) * 0.5f - pr.y) / vy;
                lts[2] = logf((t[2] - t[0]) / pr.z) / 0.2f;
                lts[3] = logf((t[3] - t[1]) / pr.w) / 0.2f;
                lts[4] = logf(t[4] / pr.z + 0.1f) / 0.2f;
                lts[5] = logf(t[5] / pr.w + 0.1f) / 0.2f;
                lts[6] = logf(t[6] / pr.z + 0.1f) / 0.2f;
                lts[7] = logf(t[7] / pr.w + 0.1f) / 0.2f;
                lts[8] = (t[8] - pr.x) / vx;
                lts[9] = (t[9] - pr.y) / vy;
                const float* ld = loc_data + ((size_t)b * NP + p) * 10;
#pragma unroll
                for (int j = 0; j < 10; j++) {
                    float d  = __ldg(ld + j) - lts[j];
                    float ad = fabsf(d);
                    ll += (ad < 1.0f) ? (0.5f * d) * d : (ad - 0.5f);
                }
            }
            S->lc[p] = lc;
        }
        __syncwarp();
    }
    __syncthreads();

    // ---- block reduce np / ll / lcp ----
#pragma unroll
    for (int o = 16; o > 0; o >>= 1) {
        ll  += __shfl_down_sync(0xffffffffu, ll, o);
        lcp += __shfl_down_sync(0xffffffffu, lcp, o);
        np  += __shfl_down_sync(0xffffffffu, np, o);
    }
    if (lane == 0) { S->rf[wrp] = ll; S->rf2[wrp] = lcp; S->ri[wrp] = np; }
    __syncthreads();
    if (tid < 32) {
        float ll_t = S->rf[tid], lcp_t = S->rf2[tid];
        int   np_t = S->ri[tid];
#pragma unroll
        for (int o = 16; o > 0; o >>= 1) {
            ll_t  += __shfl_down_sync(0xffffffffu, ll_t, o);
            lcp_t += __shfl_down_sync(0xffffffffu, lcp_t, o);
            np_t  += __shfl_down_sync(0xffffffffu, np_t, o);
        }
        if (tid == 0) { S->rf[0] = ll_t; S->rf2[0] = lcp_t; S->bc[0] = np_t; }
    }
    __syncthreads();
    const int np_tot = S->bc[0];
    const float ll_tot = S->rf[0];
    const float lcp_tot = S->rf2[0];
    int k = 3 * np_tot;
    if (k > NP - 1) k = NP - 1;

    // ---- exact top-k sum via 3-round radix select ----
    float Ssum = 0.0f;
    if (k > 0) {
        unsigned prefix = 0u, pmask = 0u;
        const int shifts[3] = {21, 10, 0};
        const int rbits[3]  = {11, 11, 10};
        int kk = k;
        for (int r = 0; r < 3; r++) {
            for (int i = tid; i < 2048; i += NTHREADS) hist[i] = 0u;
            __syncthreads();
            const unsigned nb = 1u << rbits[r];
#pragma unroll 1
            for (int p = tid; p < 9216; p += NTHREADS) {
                bool valid = p < NP;
                unsigned bb = valid ? __float_as_uint(S->lc[p]) : 0u;
                bool sel = valid && ((bb & pmask) == prefix);
                unsigned bin = sel ? ((bb >> shifts[r]) & (nb - 1u)) : 0xffffffffu;
                unsigned grp = __match_any_sync(0xffffffffu, bin);
                if (sel && lane == (__ffs(grp) - 1))
                    atomicAdd(&hist[bin], (unsigned)__popc(grp));
            }
            __syncthreads();
            unsigned h0 = hist[tid * 2 + 0], h1 = hist[tid * 2 + 1];
            unsigned sloc = h0 + h1;
            unsigned suf = sloc;
#pragma unroll
            for (int o = 1; o < 32; o <<= 1) {
                unsigned v = __shfl_down_sync(0xffffffffu, suf, o);
                if (lane + o < 32) suf += v;
            }
            if (lane == 0) S->gsum[wrp] = suf;
            __syncthreads();
            unsigned above = 0;
            for (int w = wrp + 1; w < NWARPS; w++) above += S->gsum[w];
            unsigned excl1 = above + (suf - sloc);
            unsigned excl0 = excl1 + h1;
            unsigned ukk = (unsigned)kk;
            if (excl1 < ukk && ukk <= excl1 + h1) { S->bc[1] = tid * 2 + 1; S->bc[2] = (int)(ukk - excl1); }
            if (excl0 < ukk && ukk <= excl0 + h0) { S->bc[1] = tid * 2 + 0; S->bc[2] = (int)(ukk - excl0); }
            __syncthreads();
            int chosen = S->bc[1];
            kk = S->bc[2];
            prefix |= ((unsigned)chosen) << shifts[r];
            pmask  |= ((1u << rbits[r]) - 1u) << shifts[r];
            __syncthreads();
        }
        const float tv = __uint_as_float(prefix);
        float sgt = 0.0f;
        int   cgt = 0;
#pragma unroll 1
        for (int p = tid; p < NP; p += NTHREADS) {
            float v = S->lc[p];
            if (__float_as_uint(v) > prefix) { sgt += v; cgt++; }
        }
#pragma unroll
        for (int o = 16; o > 0; o >>= 1) {
            sgt += __shfl_down_sync(0xffffffffu, sgt, o);
            cgt += __shfl_down_sync(0xffffffffu, cgt, o);
        }
        if (lane == 0) { S->rf[wrp] = sgt; S->ri[wrp] = cgt; }
        __syncthreads();
        if (tid == 0) {
            float sgt_t = 0.0f;
            int   cgt_t = 0;
            for (int w = 0; w < NWARPS; w++) { sgt_t += S->rf[w]; cgt_t += S->ri[w]; }
            Ssum = sgt_t + (float)(k - cgt_t) * tv;
        }
    }

    // ---- publish per-batch partials; last CTA finalizes ----
    __shared__ bool slast;
    if (tid == 0) {
        g_bll[b] = ll_tot;
        g_blc[b] = lcp_tot + Ssum;
        g_bnp[b] = np_tot;
        __threadfence();
        unsigned t = atomicAdd(&g_arrive, 1u);
        slast = (t == gridDim.x - 1);
        if (slast) g_arrive = 0u;
    }
    __syncthreads();
    if (slast) {
        float fll = 0.0f, flc = 0.0f;
        int   fnp = 0;
        for (int i = tid; i < (int)gridDim.x; i += NTHREADS) {
            fll += g_bll[i]; flc += g_blc[i]; fnp += g_bnp[i];
        }
#pragma unroll
        for (int o = 16; o > 0; o >>= 1) {
            fll += __shfl_down_sync(0xffffffffu, fll, o);
            flc += __shfl_down_sync(0xffffffffu, flc, o);
            fnp += __shfl_down_sync(0xffffffffu, fnp, o);
        }
        if (lane == 0) { S->rf[wrp] = fll; S->rf2[wrp] = flc; S->ri[wrp] = fnp; }
        __syncthreads();
        if (tid == 0) {
            float tll = 0.0f, tlc = 0.0f;
            int tnp = 0;
            for (int w = 0; w < NWARPS; w++) { tll += S->rf[w]; tlc += S->rf2[w]; tnp += S->ri[w]; }
            float N = (float)tnp;
            out[0] = tll / N;
            out[1] = tlc / N;
        }
    }
}

extern "C" void kernel_launch(void* const* d_in, const int* in_sizes, int n_in,
                              void* d_out, int out_size) {
    const float* loc     = (const float*)d_in[0];
    const float* conf    = (const float*)d_in[1];
    const float* priors  = (const float*)d_in[2];
    const float* targets = (const float*)d_in[3];
    const int B = in_sizes[0] / (NP * 10);

    cudaFuncSetAttribute(mb_main, cudaFuncAttributeMaxDynamicSharedMemorySize,
                         (int)sizeof(Smem));
    mb_main<<<B, NTHREADS, sizeof(Smem)>>>(loc, conf, priors, targets, (float*)d_out);
}